// round 3
// baseline (speedup 1.0000x reference)
#include <cuda_runtime.h>
#include <cuda_bf16.h>
#include <math_constants.h>

// Problem constants
#define BATCH 4
#define SEQ   2048
#define CDIM  1024
#define NHEAD 16
#define HDIM  64
#define N3C   3072

// Scratch in [B,H,T,D] layout: 4*16*2048*64 = 8388608 floats each
__device__ float g_Q[BATCH * NHEAD * SEQ * HDIM];
__device__ float g_K[BATCH * NHEAD * SEQ * HDIM];
__device__ float g_V[BATCH * NHEAD * SEQ * HDIM];
__device__ float g_O[BATCH * NHEAD * SEQ * HDIM];

// ---------------------------------------------------------------------------
// Kernel 1: QKV GEMM  [8192,1024] @ [1024,3072] + bias, scatter to Q/K/V
// 128x128 tile, BK=8, 256 threads, 8x8 per thread, DOUBLE-BUFFERED smem.
// ---------------------------------------------------------------------------
__global__ __launch_bounds__(256) void qkv_gemm(
    const float* __restrict__ X,    // [8192, 1024]
    const float* __restrict__ W,    // [1024, 3072]
    const float* __restrict__ bias) // [3072]
{
    __shared__ float As[2][8][128];
    __shared__ float Bs[2][8][128];

    const int tid = threadIdx.x;
    const int tx = tid & 15;        // 0..15 -> N
    const int ty = tid >> 4;        // 0..15 -> M
    const int bm = blockIdx.y * 128;
    const int bn = blockIdx.x * 128;

    const int arow = tid >> 1;
    const int ak4  = (tid & 1) * 4;
    const int bkr   = tid >> 5;
    const int bcol4 = (tid & 31) * 4;

    const float* Aptr = X + (size_t)(bm + arow) * CDIM + ak4;
    const float* Bptr = W + (size_t)bkr * N3C + bn + bcol4;

    float acc[8][8];
    #pragma unroll
    for (int i = 0; i < 8; i++)
        #pragma unroll
        for (int j = 0; j < 8; j++) acc[i][j] = 0.f;

    // Prologue: fill buffer 0
    {
        float4 a = *(const float4*)(Aptr);
        float4 b = *(const float4*)(Bptr);
        As[0][ak4 + 0][arow] = a.x;
        As[0][ak4 + 1][arow] = a.y;
        As[0][ak4 + 2][arow] = a.z;
        As[0][ak4 + 3][arow] = a.w;
        *(float4*)&Bs[0][bkr][bcol4] = b;
    }
    __syncthreads();

    int cur = 0;
    for (int k0 = 0; k0 < CDIM; k0 += 8) {
        float4 aN, bN;
        const bool has_next = (k0 + 8) < CDIM;
        if (has_next) {
            aN = *(const float4*)(Aptr + (k0 + 8));
            bN = *(const float4*)(Bptr + (size_t)(k0 + 8) * N3C);
        }

        #pragma unroll
        for (int k = 0; k < 8; k++) {
            float4 a0 = *(float4*)&As[cur][k][ty * 4];
            float4 a1 = *(float4*)&As[cur][k][64 + ty * 4];
            float4 b0 = *(float4*)&Bs[cur][k][tx * 4];
            float4 b1 = *(float4*)&Bs[cur][k][64 + tx * 4];
            float rm[8] = {a0.x, a0.y, a0.z, a0.w, a1.x, a1.y, a1.z, a1.w};
            float rn[8] = {b0.x, b0.y, b0.z, b0.w, b1.x, b1.y, b1.z, b1.w};
            #pragma unroll
            for (int i = 0; i < 8; i++)
                #pragma unroll
                for (int j = 0; j < 8; j++)
                    acc[i][j] += rm[i] * rn[j];
        }

        if (has_next) {
            const int nxt = cur ^ 1;
            As[nxt][ak4 + 0][arow] = aN.x;
            As[nxt][ak4 + 1][arow] = aN.y;
            As[nxt][ak4 + 2][arow] = aN.z;
            As[nxt][ak4 + 3][arow] = aN.w;
            *(float4*)&Bs[nxt][bkr][bcol4] = bN;
            __syncthreads();
            cur = nxt;
        }
    }

    // Epilogue: scatter into g_Q / g_K / g_V with head layout.
    // Q gets the softmax scale (1/sqrt(64) = 0.125) folded in.
    #pragma unroll
    for (int i = 0; i < 8; i++) {
        const int row = bm + ((i < 4) ? (ty * 4 + i) : (64 + ty * 4 + (i - 4)));
        const int bb = row >> 11;       // / 2048
        const int t  = row & 2047;
        #pragma unroll
        for (int jb = 0; jb < 2; jb++) {
            const int col = bn + jb * 64 + tx * 4;
            float4 b4 = *(const float4*)(bias + col);
            float v0 = acc[i][jb * 4 + 0] + b4.x;
            float v1 = acc[i][jb * 4 + 1] + b4.y;
            float v2 = acc[i][jb * 4 + 2] + b4.z;
            float v3 = acc[i][jb * 4 + 3] + b4.w;
            const int part = col >> 10;      // 0=Q 1=K 2=V
            const int cc = col & 1023;
            const int h = cc >> 6;
            const int d = cc & 63;
            if (part == 0) { v0 *= 0.125f; v1 *= 0.125f; v2 *= 0.125f; v3 *= 0.125f; }
            float* dst = (part == 0) ? g_Q : ((part == 1) ? g_K : g_V);
            const int idx = ((bb * NHEAD + h) * SEQ + t) * HDIM + d;
            *(float4*)&dst[idx] = make_float4(v0, v1, v2, v3);
        }
    }
}

// ---------------------------------------------------------------------------
// Kernel 2: causal flash attention fp32.
// One query row per thread, 128 rows per block, K/V in 64-row smem tiles.
// Online softmax in 16-key chunks. Q pre-scaled by 0.125.
// grid: (SEQ/128 = 16, B*H = 64), block: 128 threads.
// Longest-job-first: qt is REVERSED vs blockIdx.x so heavy CTAs launch first.
// ---------------------------------------------------------------------------
__global__ __launch_bounds__(128) void attn_kernel()
{
    const int bh  = blockIdx.y;
    const int qt  = (SEQ / 128 - 1) - blockIdx.x;   // heavy tiles first
    const int tid = threadIdx.x;
    const int qrow = qt * 128 + tid;

    __shared__ float4 Ks[64 * 16];   // 64 keys x 64 dims
    __shared__ float4 Vs[64 * 16];

    // Load this thread's query row into registers (uncoalesced but tiny traffic)
    const float4* Qb = (const float4*)(g_Q + ((size_t)bh * SEQ + qrow) * HDIM);
    float q[64];
    #pragma unroll
    for (int i = 0; i < 16; i++) {
        float4 t4 = Qb[i];
        q[i * 4 + 0] = t4.x; q[i * 4 + 1] = t4.y;
        q[i * 4 + 2] = t4.z; q[i * 4 + 3] = t4.w;
    }

    float o[64];
    #pragma unroll
    for (int d = 0; d < 64; d++) o[d] = 0.f;
    float m = -CUDART_INF_F;
    float l = 0.f;

    const int ktmax = (qt * 128 + 127) >> 6;   // inclusive

    for (int kt = 0; kt <= ktmax; kt++) {
        const float4* Kg = (const float4*)(g_K + ((size_t)bh * SEQ + kt * 64) * HDIM);
        const float4* Vg = (const float4*)(g_V + ((size_t)bh * SEQ + kt * 64) * HDIM);
        __syncthreads();
        #pragma unroll
        for (int l4 = 0; l4 < 8; l4++) {
            const int idx = l4 * 128 + tid;
            Ks[idx] = Kg[idx];
            Vs[idx] = Vg[idx];
        }
        __syncthreads();

        const bool full = (kt * 64 + 63) <= qrow;   // no masking needed

        #pragma unroll
        for (int ch = 0; ch < 4; ch++) {
            float s[16];
            float tmax = -CUDART_INF_F;
            #pragma unroll
            for (int jj = 0; jj < 16; jj++) {
                const int cj = ch * 16 + jj;
                float acc = 0.f;
                #pragma unroll
                for (int d4 = 0; d4 < 16; d4++) {
                    float4 k4 = Ks[cj * 16 + d4];
                    acc += q[d4 * 4 + 0] * k4.x;
                    acc += q[d4 * 4 + 1] * k4.y;
                    acc += q[d4 * 4 + 2] * k4.z;
                    acc += q[d4 * 4 + 3] * k4.w;
                }
                if (!full && (kt * 64 + cj) > qrow) acc = -CUDART_INF_F;
                s[jj] = acc;
                tmax = fmaxf(tmax, acc);
            }
            const float mn = fmaxf(m, tmax);
            if (mn > m) {
                const float alpha = __expf(m - mn);  // exp(-inf)=0 on first hit
                l *= alpha;
                #pragma unroll
                for (int d = 0; d < 64; d++) o[d] *= alpha;
                m = mn;
            }
            #pragma unroll
            for (int jj = 0; jj < 16; jj++) {
                const int cj = ch * 16 + jj;
                const float p = __expf(s[jj] - m);   // masked keys -> exp(-inf)=0
                l += p;
                #pragma unroll
                for (int d4 = 0; d4 < 16; d4++) {
                    float4 v4 = Vs[cj * 16 + d4];
                    o[d4 * 4 + 0] += p * v4.x;
                    o[d4 * 4 + 1] += p * v4.y;
                    o[d4 * 4 + 2] += p * v4.z;
                    o[d4 * 4 + 3] += p * v4.w;
                }
            }
        }
    }

    const float inv = 1.0f / l;   // l >= exp(0) contribution from key 0
    float4* Ob = (float4*)(g_O + ((size_t)bh * SEQ + qrow) * HDIM);
    #pragma unroll
    for (int d4 = 0; d4 < 16; d4++) {
        Ob[d4] = make_float4(o[d4 * 4 + 0] * inv, o[d4 * 4 + 1] * inv,
                             o[d4 * 4 + 2] * inv, o[d4 * 4 + 3] * inv);
    }
}

// ---------------------------------------------------------------------------
// Kernel 3: output projection.  gather(g_O)[8192,1024] @ W_out[1024,1024] + b
// Same double-buffered SGEMM; A gathered from [B,H,T,D] layout on load.
// ---------------------------------------------------------------------------
__global__ __launch_bounds__(256) void out_gemm(
    const float* __restrict__ W,    // [1024, 1024]
    const float* __restrict__ bias, // [1024]
    float* __restrict__ out)        // [8192, 1024]
{
    __shared__ float As[2][8][128];
    __shared__ float Bs[2][8][128];

    const int tid = threadIdx.x;
    const int tx = tid & 15;
    const int ty = tid >> 4;
    const int bm = blockIdx.y * 128;
    const int bn = blockIdx.x * 128;

    const int arow = tid >> 1;
    const int ak4  = (tid & 1) * 4;
    const int bkr   = tid >> 5;
    const int bcol4 = (tid & 31) * 4;

    const int row = bm + arow;
    const int bb = row >> 11;
    const int t  = row & 2047;

    const float* Bptr = W + (size_t)bkr * CDIM + bn + bcol4;

    float acc[8][8];
    #pragma unroll
    for (int i = 0; i < 8; i++)
        #pragma unroll
        for (int j = 0; j < 8; j++) acc[i][j] = 0.f;

    // A gather address for channel k = k0 + ak4 (h = k>>6, d = k&63)
    auto aload = [&](int k0) -> float4 {
        const int k = k0 + ak4;
        const int h = k >> 6;
        const int d = k & 63;
        return *(const float4*)&g_O[((bb * NHEAD + h) * SEQ + t) * HDIM + d];
    };

    // Prologue
    {
        float4 a = aload(0);
        float4 b = *(const float4*)(Bptr);
        As[0][ak4 + 0][arow] = a.x;
        As[0][ak4 + 1][arow] = a.y;
        As[0][ak4 + 2][arow] = a.z;
        As[0][ak4 + 3][arow] = a.w;
        *(float4*)&Bs[0][bkr][bcol4] = b;
    }
    __syncthreads();

    int cur = 0;
    for (int k0 = 0; k0 < CDIM; k0 += 8) {
        float4 aN, bN;
        const bool has_next = (k0 + 8) < CDIM;
        if (has_next) {
            aN = aload(k0 + 8);
            bN = *(const float4*)(Bptr + (size_t)(k0 + 8) * CDIM);
        }

        #pragma unroll
        for (int kk = 0; kk < 8; kk++) {
            float4 a0 = *(float4*)&As[cur][kk][ty * 4];
            float4 a1 = *(float4*)&As[cur][kk][64 + ty * 4];
            float4 b0 = *(float4*)&Bs[cur][kk][tx * 4];
            float4 b1 = *(float4*)&Bs[cur][kk][64 + tx * 4];
            float rm[8] = {a0.x, a0.y, a0.z, a0.w, a1.x, a1.y, a1.z, a1.w};
            float rn[8] = {b0.x, b0.y, b0.z, b0.w, b1.x, b1.y, b1.z, b1.w};
            #pragma unroll
            for (int i = 0; i < 8; i++)
                #pragma unroll
                for (int j = 0; j < 8; j++)
                    acc[i][j] += rm[i] * rn[j];
        }

        if (has_next) {
            const int nxt = cur ^ 1;
            As[nxt][ak4 + 0][arow] = aN.x;
            As[nxt][ak4 + 1][arow] = aN.y;
            As[nxt][ak4 + 2][arow] = aN.z;
            As[nxt][ak4 + 3][arow] = aN.w;
            *(float4*)&Bs[nxt][bkr][bcol4] = bN;
            __syncthreads();
            cur = nxt;
        }
    }

    #pragma unroll
    for (int i = 0; i < 8; i++) {
        const int orow = bm + ((i < 4) ? (ty * 4 + i) : (64 + ty * 4 + (i - 4)));
        #pragma unroll
        for (int jb = 0; jb < 2; jb++) {
            const int col = bn + jb * 64 + tx * 4;
            float4 b4 = *(const float4*)(bias + col);
            float4 v = make_float4(acc[i][jb * 4 + 0] + b4.x,
                                   acc[i][jb * 4 + 1] + b4.y,
                                   acc[i][jb * 4 + 2] + b4.z,
                                   acc[i][jb * 4 + 3] + b4.w);
            *(float4*)&out[(size_t)orow * CDIM + col] = v;
        }
    }
}

// ---------------------------------------------------------------------------
extern "C" void kernel_launch(void* const* d_in, const int* in_sizes, int n_in,
                              void* d_out, int out_size)
{
    const float* x     = (const float*)d_in[0];
    const float* W_qkv = (const float*)d_in[1];
    const float* b_qkv = (const float*)d_in[2];
    const float* W_out = (const float*)d_in[3];
    const float* b_out = (const float*)d_in[4];
    float* out = (float*)d_out;

    // 1) QKV projection, scatter into [B,H,T,D] scratch (Q pre-scaled)
    qkv_gemm<<<dim3(N3C / 128, (BATCH * SEQ) / 128), 256>>>(x, W_qkv, b_qkv);

    // 2) causal flash attention (longest-job-first qt order)
    attn_kernel<<<dim3(SEQ / 128, BATCH * NHEAD), 128>>>();

    // 3) output projection
    out_gemm<<<dim3(CDIM / 128, (BATCH * SEQ) / 128), 256>>>(W_out, b_out, out);
}

// round 5
// speedup vs baseline: 1.7800x; 1.7800x over previous
#include <cuda_runtime.h>
#include <cuda_bf16.h>
#include <math_constants.h>
#include <cstdint>

#define BATCH 4
#define SEQ   2048
#define CDIM  1024
#define NHEAD 16
#define HDIM  64
#define N3C   3072

__device__ float g_Q[BATCH * NHEAD * SEQ * HDIM];
__device__ float g_K[BATCH * NHEAD * SEQ * HDIM];
__device__ float g_V[BATCH * NHEAD * SEQ * HDIM];
__device__ float g_O[BATCH * NHEAD * SEQ * HDIM];

// ---------------------------------------------------------------------------
// helpers
// ---------------------------------------------------------------------------
__device__ __forceinline__ uint32_t f2tf32(float f) {
    uint32_t r;
    asm("cvt.rna.tf32.f32 %0, %1;" : "=r"(r) : "f"(f));
    return r;
}

__device__ __forceinline__ void mma_tf32(float c[4],
                                         const uint32_t a[4],
                                         const uint32_t b[2]) {
    asm volatile(
        "mma.sync.aligned.m16n8k8.row.col.f32.tf32.tf32.f32 "
        "{%0,%1,%2,%3}, {%4,%5,%6,%7}, {%8,%9}, {%0,%1,%2,%3};\n"
        : "+f"(c[0]), "+f"(c[1]), "+f"(c[2]), "+f"(c[3])
        : "r"(a[0]), "r"(a[1]), "r"(a[2]), "r"(a[3]),
          "r"(b[0]), "r"(b[1]));
}

__device__ __forceinline__ unsigned long long ffma2(unsigned long long a,
                                                    unsigned long long b,
                                                    unsigned long long c) {
    unsigned long long d;
    asm("fma.rn.f32x2 %0, %1, %2, %3;" : "=l"(d) : "l"(a), "l"(b), "l"(c));
    return d;
}

__device__ __forceinline__ unsigned long long fmul2(unsigned long long a,
                                                    unsigned long long b) {
    unsigned long long d;
    asm("mul.rn.f32x2 %0, %1, %2;" : "=l"(d) : "l"(a), "l"(b));
    return d;
}

__device__ __forceinline__ unsigned long long pack2(float lo, float hi) {
    unsigned long long r;
    asm("mov.b64 %0, {%1, %2};" : "=l"(r) : "f"(lo), "f"(hi));
    return r;
}

__device__ __forceinline__ void unpack2(unsigned long long v, float& lo, float& hi) {
    asm("mov.b64 {%0, %1}, %2;" : "=f"(lo), "=f"(hi) : "l"(v));
}

#define PAD 136   // 128 + 8: row skew of 8 banks -> conflict-free fragment LDS

// ---------------------------------------------------------------------------
// Kernel 1: QKV GEMM via tf32 mma.sync. 128x128 tile, BK=16, 256 threads.
// Warps 4(M)x2(N); each warp 32x64 = 2 x 8 m16n8k8 tiles. Double-buffered.
// A staged k-major [k][m], B staged [k][n], both tf32-converted on store.
// ---------------------------------------------------------------------------
__global__ __launch_bounds__(256) void qkv_gemm(
    const float* __restrict__ X,    // [8192, 1024]
    const float* __restrict__ W,    // [1024, 3072]
    const float* __restrict__ bias) // [3072]
{
    __shared__ uint32_t As[2][16][PAD];
    __shared__ uint32_t Bs[2][16][PAD];

    const int tid = threadIdx.x;
    const int wid = tid >> 5;
    const int lane = tid & 31;
    const int g = lane >> 2;          // 0..7
    const int tig = lane & 3;         // 0..3
    const int warp_m = wid >> 1;      // 0..3
    const int warp_n = wid & 1;       // 0..1

    const int bm = blockIdx.y * 128;
    const int bn = blockIdx.x * 128;

    const int ar = tid >> 2;          // 0..63  (A rows ar, ar+64)
    const int ac = (tid & 3) * 4;     // k offset {0,4,8,12}
    const int br = tid >> 5;          // 0..7   (B k-rows br, br+8)
    const int bc = (tid & 31) * 4;    // n offset

    const float* Ap0 = X + (size_t)(bm + ar) * CDIM + ac;
    const float* Ap1 = X + (size_t)(bm + ar + 64) * CDIM + ac;
    const float* Bp0 = W + (size_t)br * N3C + bn + bc;
    const float* Bp1 = W + (size_t)(br + 8) * N3C + bn + bc;

    float acc[2][8][4];
    #pragma unroll
    for (int mt = 0; mt < 2; mt++)
        #pragma unroll
        for (int nt = 0; nt < 8; nt++)
            #pragma unroll
            for (int i = 0; i < 4; i++) acc[mt][nt][i] = 0.f;

    auto stage = [&](int buf, float4 a0, float4 a1, float4 b0, float4 b1) {
        As[buf][ac + 0][ar] = f2tf32(a0.x);
        As[buf][ac + 1][ar] = f2tf32(a0.y);
        As[buf][ac + 2][ar] = f2tf32(a0.z);
        As[buf][ac + 3][ar] = f2tf32(a0.w);
        As[buf][ac + 0][ar + 64] = f2tf32(a1.x);
        As[buf][ac + 1][ar + 64] = f2tf32(a1.y);
        As[buf][ac + 2][ar + 64] = f2tf32(a1.z);
        As[buf][ac + 3][ar + 64] = f2tf32(a1.w);
        Bs[buf][br][bc + 0] = f2tf32(b0.x);
        Bs[buf][br][bc + 1] = f2tf32(b0.y);
        Bs[buf][br][bc + 2] = f2tf32(b0.z);
        Bs[buf][br][bc + 3] = f2tf32(b0.w);
        Bs[buf][br + 8][bc + 0] = f2tf32(b1.x);
        Bs[buf][br + 8][bc + 1] = f2tf32(b1.y);
        Bs[buf][br + 8][bc + 2] = f2tf32(b1.z);
        Bs[buf][br + 8][bc + 3] = f2tf32(b1.w);
    };

    stage(0,
          *(const float4*)(Ap0), *(const float4*)(Ap1),
          *(const float4*)(Bp0), *(const float4*)(Bp1));
    __syncthreads();

    const int am = warp_m * 32;
    const int an = warp_n * 64;

    int cur = 0;
    for (int k0 = 0; k0 < CDIM; k0 += 16) {
        float4 a0n, a1n, b0n, b1n;
        const bool has_next = (k0 + 16) < CDIM;
        if (has_next) {
            a0n = *(const float4*)(Ap0 + (k0 + 16));
            a1n = *(const float4*)(Ap1 + (k0 + 16));
            b0n = *(const float4*)(Bp0 + (size_t)(k0 + 16) * N3C);
            b1n = *(const float4*)(Bp1 + (size_t)(k0 + 16) * N3C);
        }

        #pragma unroll
        for (int kk = 0; kk < 16; kk += 8) {
            uint32_t Af[2][4], Bf[8][2];
            #pragma unroll
            for (int mt = 0; mt < 2; mt++) {
                const int m0 = am + mt * 16;
                Af[mt][0] = As[cur][kk + tig][m0 + g];
                Af[mt][1] = As[cur][kk + tig][m0 + g + 8];
                Af[mt][2] = As[cur][kk + tig + 4][m0 + g];
                Af[mt][3] = As[cur][kk + tig + 4][m0 + g + 8];
            }
            #pragma unroll
            for (int nt = 0; nt < 8; nt++) {
                const int n0 = an + nt * 8;
                Bf[nt][0] = Bs[cur][kk + tig][n0 + g];
                Bf[nt][1] = Bs[cur][kk + tig + 4][n0 + g];
            }
            #pragma unroll
            for (int mt = 0; mt < 2; mt++)
                #pragma unroll
                for (int nt = 0; nt < 8; nt++)
                    mma_tf32(acc[mt][nt], Af[mt], Bf[nt]);
        }

        if (has_next) {
            const int nxt = cur ^ 1;
            // writes go to nxt (disjoint from cur being read); barrier below
            // orders this iteration's reads of cur before next iter's writes.
            stage(nxt, a0n, a1n, b0n, b1n);
            __syncthreads();
            cur = nxt;
        }
    }

    // Epilogue: c0,c1 -> row g, cols 2*tig,2*tig+1; c2,c3 -> row g+8.
    #pragma unroll
    for (int mt = 0; mt < 2; mt++) {
        #pragma unroll
        for (int half = 0; half < 2; half++) {
            const int row = bm + am + mt * 16 + g + half * 8;
            const int bb = row >> 11;
            const int t  = row & 2047;
            #pragma unroll
            for (int nt = 0; nt < 8; nt++) {
                const int col = bn + an + nt * 8 + tig * 2;
                float v0 = acc[mt][nt][half * 2 + 0] + bias[col];
                float v1 = acc[mt][nt][half * 2 + 1] + bias[col + 1];
                const int part = col >> 10;      // 0=Q 1=K 2=V
                const int cc = col & 1023;
                const int h = cc >> 6;
                const int d = cc & 63;
                if (part == 0) { v0 *= 0.125f; v1 *= 0.125f; }
                float* dst = (part == 0) ? g_Q : ((part == 1) ? g_K : g_V);
                const int idx = ((bb * NHEAD + h) * SEQ + t) * HDIM + d;
                *(float2*)&dst[idx] = make_float2(v0, v1);
            }
        }
    }
}

// ---------------------------------------------------------------------------
// Kernel 2: causal flash attention, packed f32x2 FMA (FFMA2), LJF CTA order.
// 1 query row/thread, 128 rows/block, 64-key smem tiles.
// Layout: row = 64 floats = 32 u64 pairs; pair p covers dims {2p, 2p+1}.
// ---------------------------------------------------------------------------
__global__ __launch_bounds__(128) void attn_kernel()
{
    const int bh  = blockIdx.y;
    const int qt  = (SEQ / 128 - 1) - blockIdx.x;   // heavy tiles first
    const int tid = threadIdx.x;
    const int qrow = qt * 128 + tid;

    __shared__ unsigned long long Ks[64 * 32];   // 16 KB
    __shared__ unsigned long long Vs[64 * 32];   // 16 KB

    const ulonglong2* Qb = (const ulonglong2*)(g_Q + ((size_t)bh * SEQ + qrow) * HDIM);
    unsigned long long q2[32];
    #pragma unroll
    for (int i = 0; i < 16; i++) {
        ulonglong2 u = Qb[i];
        q2[i * 2 + 0] = u.x;
        q2[i * 2 + 1] = u.y;
    }

    unsigned long long o2[32];
    #pragma unroll
    for (int i = 0; i < 32; i++) o2[i] = 0ull;   // (0.f, 0.f)
    float m = -CUDART_INF_F;
    float l = 0.f;

    const int ktmax = (qt * 128 + 127) >> 6;

    for (int kt = 0; kt <= ktmax; kt++) {
        const ulonglong2* Kg = (const ulonglong2*)(g_K + ((size_t)bh * SEQ + kt * 64) * HDIM);
        const ulonglong2* Vg = (const ulonglong2*)(g_V + ((size_t)bh * SEQ + kt * 64) * HDIM);
        __syncthreads();
        #pragma unroll
        for (int l4 = 0; l4 < 8; l4++) {
            const int idx = l4 * 128 + tid;      // 1024 ull2 slots total
            ((ulonglong2*)Ks)[idx] = Kg[idx];
            ((ulonglong2*)Vs)[idx] = Vg[idx];
        }
        __syncthreads();

        const bool full = (kt * 64 + 63) <= qrow;

        #pragma unroll
        for (int ch = 0; ch < 4; ch++) {
            float s[16];
            float tmax = -CUDART_INF_F;
            #pragma unroll
            for (int jj = 0; jj < 16; jj++) {
                const int cj = ch * 16 + jj;
                unsigned long long accA = 0ull, accB = 0ull;
                #pragma unroll
                for (int p = 0; p < 32; p += 2) {
                    accA = ffma2(q2[p + 0], Ks[cj * 32 + p + 0], accA);
                    accB = ffma2(q2[p + 1], Ks[cj * 32 + p + 1], accB);
                }
                float a0, a1, b0, b1;
                unpack2(accA, a0, a1);
                unpack2(accB, b0, b1);
                float sc = (a0 + a1) + (b0 + b1);
                if (!full && (kt * 64 + cj) > qrow) sc = -CUDART_INF_F;
                s[jj] = sc;
                tmax = fmaxf(tmax, sc);
            }
            const float mn = fmaxf(m, tmax);
            if (mn > m) {
                const float alpha = __expf(m - mn);   // exp(-inf)=0 first time
                l *= alpha;
                const unsigned long long al2 = pack2(alpha, alpha);
                #pragma unroll
                for (int i = 0; i < 32; i++) o2[i] = fmul2(o2[i], al2);
                m = mn;
            }
            #pragma unroll
            for (int jj = 0; jj < 16; jj++) {
                const int cj = ch * 16 + jj;
                const float p = __expf(s[jj] - m);    // masked -> 0
                l += p;
                const unsigned long long p2 = pack2(p, p);
                #pragma unroll
                for (int d = 0; d < 32; d++)
                    o2[d] = ffma2(p2, Vs[cj * 32 + d], o2[d]);
            }
        }
    }

    const float inv = 1.0f / l;
    float4* Ob = (float4*)(g_O + ((size_t)bh * SEQ + qrow) * HDIM);
    #pragma unroll
    for (int i = 0; i < 16; i++) {
        float x0, x1, x2, x3;
        unpack2(o2[i * 2 + 0], x0, x1);
        unpack2(o2[i * 2 + 1], x2, x3);
        Ob[i] = make_float4(x0 * inv, x1 * inv, x2 * inv, x3 * inv);
    }
}

// ---------------------------------------------------------------------------
// Kernel 3: output projection via tf32 mma; A gathered from g_O [B,H,T,D].
// ---------------------------------------------------------------------------
__global__ __launch_bounds__(256) void out_gemm(
    const float* __restrict__ W,    // [1024, 1024]
    const float* __restrict__ bias, // [1024]
    float* __restrict__ out)        // [8192, 1024]
{
    __shared__ uint32_t As[2][16][PAD];
    __shared__ uint32_t Bs[2][16][PAD];

    const int tid = threadIdx.x;
    const int wid = tid >> 5;
    const int lane = tid & 31;
    const int g = lane >> 2;
    const int tig = lane & 3;
    const int warp_m = wid >> 1;
    const int warp_n = wid & 1;

    const int bm = blockIdx.y * 128;
    const int bn = blockIdx.x * 128;

    const int ar = tid >> 2;
    const int ac = (tid & 3) * 4;
    const int br = tid >> 5;
    const int bc = (tid & 31) * 4;

    const float* Bp0 = W + (size_t)br * CDIM + bn + bc;
    const float* Bp1 = W + (size_t)(br + 8) * CDIM + bn + bc;

    const int row0 = bm + ar;
    const int row1 = bm + ar + 64;
    const int bb0 = row0 >> 11, t0 = row0 & 2047;
    const int bb1 = row1 >> 11, t1 = row1 & 2047;

    auto aload = [&](int k0, int which) -> float4 {
        const int k = k0 + ac;
        const int h = k >> 6;
        const int d = k & 63;
        const int bb = which ? bb1 : bb0;
        const int t  = which ? t1 : t0;
        return *(const float4*)&g_O[((bb * NHEAD + h) * SEQ + t) * HDIM + d];
    };

    float acc[2][8][4];
    #pragma unroll
    for (int mt = 0; mt < 2; mt++)
        #pragma unroll
        for (int nt = 0; nt < 8; nt++)
            #pragma unroll
            for (int i = 0; i < 4; i++) acc[mt][nt][i] = 0.f;

    auto stage = [&](int buf, float4 a0, float4 a1, float4 b0, float4 b1) {
        As[buf][ac + 0][ar] = f2tf32(a0.x);
        As[buf][ac + 1][ar] = f2tf32(a0.y);
        As[buf][ac + 2][ar] = f2tf32(a0.z);
        As[buf][ac + 3][ar] = f2tf32(a0.w);
        As[buf][ac + 0][ar + 64] = f2tf32(a1.x);
        As[buf][ac + 1][ar + 64] = f2tf32(a1.y);
        As[buf][ac + 2][ar + 64] = f2tf32(a1.z);
        As[buf][ac + 3][ar + 64] = f2tf32(a1.w);
        Bs[buf][br][bc + 0] = f2tf32(b0.x);
        Bs[buf][br][bc + 1] = f2tf32(b0.y);
        Bs[buf][br][bc + 2] = f2tf32(b0.z);
        Bs[buf][br][bc + 3] = f2tf32(b0.w);
        Bs[buf][br + 8][bc + 0] = f2tf32(b1.x);
        Bs[buf][br + 8][bc + 1] = f2tf32(b1.y);
        Bs[buf][br + 8][bc + 2] = f2tf32(b1.z);
        Bs[buf][br + 8][bc + 3] = f2tf32(b1.w);
    };

    stage(0, aload(0, 0), aload(0, 1),
          *(const float4*)(Bp0), *(const float4*)(Bp1));
    __syncthreads();

    const int am = warp_m * 32;
    const int an = warp_n * 64;

    int cur = 0;
    for (int k0 = 0; k0 < CDIM; k0 += 16) {
        float4 a0n, a1n, b0n, b1n;
        const bool has_next = (k0 + 16) < CDIM;
        if (has_next) {
            a0n = aload(k0 + 16, 0);
            a1n = aload(k0 + 16, 1);
            b0n = *(const float4*)(Bp0 + (size_t)(k0 + 16) * CDIM);
            b1n = *(const float4*)(Bp1 + (size_t)(k0 + 16) * CDIM);
        }

        #pragma unroll
        for (int kk = 0; kk < 16; kk += 8) {
            uint32_t Af[2][4], Bf[8][2];
            #pragma unroll
            for (int mt = 0; mt < 2; mt++) {
                const int m0 = am + mt * 16;
                Af[mt][0] = As[cur][kk + tig][m0 + g];
                Af[mt][1] = As[cur][kk + tig][m0 + g + 8];
                Af[mt][2] = As[cur][kk + tig + 4][m0 + g];
                Af[mt][3] = As[cur][kk + tig + 4][m0 + g + 8];
            }
            #pragma unroll
            for (int nt = 0; nt < 8; nt++) {
                const int n0 = an + nt * 8;
                Bf[nt][0] = Bs[cur][kk + tig][n0 + g];
                Bf[nt][1] = Bs[cur][kk + tig + 4][n0 + g];
            }
            #pragma unroll
            for (int mt = 0; mt < 2; mt++)
                #pragma unroll
                for (int nt = 0; nt < 8; nt++)
                    mma_tf32(acc[mt][nt], Af[mt], Bf[nt]);
        }

        if (has_next) {
            const int nxt = cur ^ 1;
            stage(nxt, a0n, a1n, b0n, b1n);
            __syncthreads();
            cur = nxt;
        }
    }

    #pragma unroll
    for (int mt = 0; mt < 2; mt++) {
        #pragma unroll
        for (int half = 0; half < 2; half++) {
            const int row = bm + am + mt * 16 + g + half * 8;
            #pragma unroll
            for (int nt = 0; nt < 8; nt++) {
                const int col = bn + an + nt * 8 + tig * 2;
                float v0 = acc[mt][nt][half * 2 + 0] + bias[col];
                float v1 = acc[mt][nt][half * 2 + 1] + bias[col + 1];
                *(float2*)&out[(size_t)row * CDIM + col] = make_float2(v0, v1);
            }
        }
    }
}

// ---------------------------------------------------------------------------
extern "C" void kernel_launch(void* const* d_in, const int* in_sizes, int n_in,
                              void* d_out, int out_size)
{
    const float* x     = (const float*)d_in[0];
    const float* W_qkv = (const float*)d_in[1];
    const float* b_qkv = (const float*)d_in[2];
    const float* W_out = (const float*)d_in[3];
    const float* b_out = (const float*)d_in[4];
    float* out = (float*)d_out;

    qkv_gemm<<<dim3(N3C / 128, (BATCH * SEQ) / 128), 256>>>(x, W_qkv, b_qkv);
    attn_kernel<<<dim3(SEQ / 128, BATCH * NHEAD), 128>>>();
    out_gemm<<<dim3(CDIM / 128, (BATCH * SEQ) / 128), 256>>>(W_out, b_out, out);
}

// round 7
// speedup vs baseline: 4.6534x; 2.6142x over previous
#include <cuda_runtime.h>
#include <cuda_bf16.h>
#include <cuda_fp16.h>
#include <math_constants.h>
#include <cstdint>
#include <cstring>

#define BATCH 4
#define SEQ   2048
#define CDIM  1024
#define NHEAD 16
#define HDIM  64
#define N3C   3072

__device__ float g_Q[BATCH * NHEAD * SEQ * HDIM];
__device__ float g_K[BATCH * NHEAD * SEQ * HDIM];
__device__ float g_V[BATCH * NHEAD * SEQ * HDIM];
__device__ float g_O[BATCH * NHEAD * SEQ * HDIM];

// ---------------------------------------------------------------------------
// helpers
// ---------------------------------------------------------------------------
__device__ __forceinline__ uint32_t f2tf32(float f) {
    uint32_t r;
    asm("cvt.rna.tf32.f32 %0, %1;" : "=r"(r) : "f"(f));
    return r;
}

__device__ __forceinline__ uint32_t h2u(__half2 h) {
    uint32_t r;
    memcpy(&r, &h, 4);
    return r;
}

__device__ __forceinline__ void mma_tf32(float c[4],
                                         const uint32_t a[4],
                                         uint32_t b0, uint32_t b1) {
    asm volatile(
        "mma.sync.aligned.m16n8k8.row.col.f32.tf32.tf32.f32 "
        "{%0,%1,%2,%3}, {%4,%5,%6,%7}, {%8,%9}, {%0,%1,%2,%3};\n"
        : "+f"(c[0]), "+f"(c[1]), "+f"(c[2]), "+f"(c[3])
        : "r"(a[0]), "r"(a[1]), "r"(a[2]), "r"(a[3]),
          "r"(b0), "r"(b1));
}

__device__ __forceinline__ void mma_f16(float c[4],
                                        const uint32_t a[4],
                                        uint32_t b0, uint32_t b1) {
    asm volatile(
        "mma.sync.aligned.m16n8k16.row.col.f32.f16.f16.f32 "
        "{%0,%1,%2,%3}, {%4,%5,%6,%7}, {%8,%9}, {%0,%1,%2,%3};\n"
        : "+f"(c[0]), "+f"(c[1]), "+f"(c[2]), "+f"(c[3])
        : "r"(a[0]), "r"(a[1]), "r"(a[2]), "r"(a[3]),
          "r"(b0), "r"(b1));
}

#define PAD 136   // GEMM smem row skew

// ---------------------------------------------------------------------------
// Kernel 1: QKV GEMM via tf32 mma.sync. 128x128 tile, BK=16, 256 threads.
// ---------------------------------------------------------------------------
__global__ __launch_bounds__(256) void qkv_gemm(
    const float* __restrict__ X,    // [8192, 1024]
    const float* __restrict__ W,    // [1024, 3072]
    const float* __restrict__ bias) // [3072]
{
    __shared__ uint32_t As[2][16][PAD];
    __shared__ uint32_t Bs[2][16][PAD];

    const int tid = threadIdx.x;
    const int wid = tid >> 5;
    const int lane = tid & 31;
    const int g = lane >> 2;
    const int tig = lane & 3;
    const int warp_m = wid >> 1;
    const int warp_n = wid & 1;

    const int bm = blockIdx.y * 128;
    const int bn = blockIdx.x * 128;

    const int ar = tid >> 2;
    const int ac = (tid & 3) * 4;
    const int br = tid >> 5;
    const int bc = (tid & 31) * 4;

    const float* Ap0 = X + (size_t)(bm + ar) * CDIM + ac;
    const float* Ap1 = X + (size_t)(bm + ar + 64) * CDIM + ac;
    const float* Bp0 = W + (size_t)br * N3C + bn + bc;
    const float* Bp1 = W + (size_t)(br + 8) * N3C + bn + bc;

    float acc[2][8][4];
    #pragma unroll
    for (int mt = 0; mt < 2; mt++)
        #pragma unroll
        for (int nt = 0; nt < 8; nt++)
            #pragma unroll
            for (int i = 0; i < 4; i++) acc[mt][nt][i] = 0.f;

    auto stage = [&](int buf, float4 a0, float4 a1, float4 b0, float4 b1) {
        As[buf][ac + 0][ar] = f2tf32(a0.x);
        As[buf][ac + 1][ar] = f2tf32(a0.y);
        As[buf][ac + 2][ar] = f2tf32(a0.z);
        As[buf][ac + 3][ar] = f2tf32(a0.w);
        As[buf][ac + 0][ar + 64] = f2tf32(a1.x);
        As[buf][ac + 1][ar + 64] = f2tf32(a1.y);
        As[buf][ac + 2][ar + 64] = f2tf32(a1.z);
        As[buf][ac + 3][ar + 64] = f2tf32(a1.w);
        Bs[buf][br][bc + 0] = f2tf32(b0.x);
        Bs[buf][br][bc + 1] = f2tf32(b0.y);
        Bs[buf][br][bc + 2] = f2tf32(b0.z);
        Bs[buf][br][bc + 3] = f2tf32(b0.w);
        Bs[buf][br + 8][bc + 0] = f2tf32(b1.x);
        Bs[buf][br + 8][bc + 1] = f2tf32(b1.y);
        Bs[buf][br + 8][bc + 2] = f2tf32(b1.z);
        Bs[buf][br + 8][bc + 3] = f2tf32(b1.w);
    };

    stage(0,
          *(const float4*)(Ap0), *(const float4*)(Ap1),
          *(const float4*)(Bp0), *(const float4*)(Bp1));
    __syncthreads();

    const int am = warp_m * 32;
    const int an = warp_n * 64;

    int cur = 0;
    for (int k0 = 0; k0 < CDIM; k0 += 16) {
        float4 a0n, a1n, b0n, b1n;
        const bool has_next = (k0 + 16) < CDIM;
        if (has_next) {
            a0n = *(const float4*)(Ap0 + (k0 + 16));
            a1n = *(const float4*)(Ap1 + (k0 + 16));
            b0n = *(const float4*)(Bp0 + (size_t)(k0 + 16) * N3C);
            b1n = *(const float4*)(Bp1 + (size_t)(k0 + 16) * N3C);
        }

        #pragma unroll
        for (int kk = 0; kk < 16; kk += 8) {
            uint32_t Af[2][4], Bf[8][2];
            #pragma unroll
            for (int mt = 0; mt < 2; mt++) {
                const int m0 = am + mt * 16;
                Af[mt][0] = As[cur][kk + tig][m0 + g];
                Af[mt][1] = As[cur][kk + tig][m0 + g + 8];
                Af[mt][2] = As[cur][kk + tig + 4][m0 + g];
                Af[mt][3] = As[cur][kk + tig + 4][m0 + g + 8];
            }
            #pragma unroll
            for (int nt = 0; nt < 8; nt++) {
                const int n0 = an + nt * 8;
                Bf[nt][0] = Bs[cur][kk + tig][n0 + g];
                Bf[nt][1] = Bs[cur][kk + tig + 4][n0 + g];
            }
            #pragma unroll
            for (int mt = 0; mt < 2; mt++)
                #pragma unroll
                for (int nt = 0; nt < 8; nt++)
                    mma_tf32(acc[mt][nt], Af[mt], Bf[nt][0], Bf[nt][1]);
        }

        if (has_next) {
            const int nxt = cur ^ 1;
            stage(nxt, a0n, a1n, b0n, b1n);
            __syncthreads();
            cur = nxt;
        }
    }

    #pragma unroll
    for (int mt = 0; mt < 2; mt++) {
        #pragma unroll
        for (int half = 0; half < 2; half++) {
            const int row = bm + am + mt * 16 + g + half * 8;
            const int bb = row >> 11;
            const int t  = row & 2047;
            #pragma unroll
            for (int nt = 0; nt < 8; nt++) {
                const int col = bn + an + nt * 8 + tig * 2;
                float v0 = acc[mt][nt][half * 2 + 0] + bias[col];
                float v1 = acc[mt][nt][half * 2 + 1] + bias[col + 1];
                const int part = col >> 10;
                const int cc = col & 1023;
                const int h = cc >> 6;
                const int d = cc & 63;
                if (part == 0) { v0 *= 0.125f; v1 *= 0.125f; }
                float* dst = (part == 0) ? g_Q : ((part == 1) ? g_K : g_V);
                const int idx = ((bb * NHEAD + h) * SEQ + t) * HDIM + d;
                *(float2*)&dst[idx] = make_float2(v0, v1);
            }
        }
    }
}

// ---------------------------------------------------------------------------
// Kernel 2: tensor-core causal flash attention.
// QK: tf32 m16n8k8 (K in smem [key][dim], no transpose).
// PV: f16 m16n8k16 (V in smem transposed [dim][key] as half; P fragments are
//     repacked S C-fragments -> zero shuffles).
// 8 warps x 16 q rows = 128 q rows per CTA; 64-key tiles; warps skip tiles
// that are fully masked for their rows. grid (16, 64), LJF qt; block 256.
// ---------------------------------------------------------------------------
#define KSTRIDE 68   // Ks row stride (floats)
#define VSTRIDE 72   // VsT row stride (halves)

__global__ __launch_bounds__(256) void attn_kernel()
{
    const int bh  = blockIdx.y;
    const int qt  = (SEQ / 128 - 1) - blockIdx.x;
    const int tid = threadIdx.x;
    const int wid = tid >> 5;
    const int lane = tid & 31;
    const int g   = lane >> 2;     // 0..7
    const int tig = lane & 3;      // 0..3

    const int qbase = qt * 128;
    const int wbase = qbase + wid * 16;
    const int row0  = wbase + g;
    const int row1  = row0 + 8;

    __shared__ uint32_t Ks[64][KSTRIDE];   // tf32 [key][dim]
    __shared__ __half   VsT[64][VSTRIDE];  // f16  [dim][key]

    const float* Qb = g_Q + (size_t)bh * SEQ * HDIM;
    const float* Kb = g_K + (size_t)bh * SEQ * HDIM;
    const float* Vb = g_V + (size_t)bh * SEQ * HDIM;

    // Q fragments, resident whole loop. a0=A[g][tig], a1=A[g+8][tig],
    // a2=A[g][tig+4], a3=A[g+8][tig+4] per 8-wide k chunk.
    uint32_t qf[8][4];
    #pragma unroll
    for (int kt8 = 0; kt8 < 8; kt8++) {
        qf[kt8][0] = f2tf32(Qb[(size_t)row0 * HDIM + kt8 * 8 + tig]);
        qf[kt8][1] = f2tf32(Qb[(size_t)row1 * HDIM + kt8 * 8 + tig]);
        qf[kt8][2] = f2tf32(Qb[(size_t)row0 * HDIM + kt8 * 8 + tig + 4]);
        qf[kt8][3] = f2tf32(Qb[(size_t)row1 * HDIM + kt8 * 8 + tig + 4]);
    }

    float of[8][4];
    #pragma unroll
    for (int dt = 0; dt < 8; dt++)
        #pragma unroll
        for (int i = 0; i < 4; i++) of[dt][i] = 0.f;

    float m0 = -CUDART_INF_F, m1 = -CUDART_INF_F;
    float l0 = 0.f, l1 = 0.f;

    const int ktmax = (qbase + 127) >> 6;   // inclusive

    for (int kt = 0; kt <= ktmax; kt++) {
        __syncthreads();
        // stage K (tf32) and V^T (f16): 64 keys x 64 dims
        #pragma unroll
        for (int i = 0; i < 4; i++) {
            const int idx = tid + i * 256;      // 0..1023
            const int key = idx >> 4;
            const int c4  = (idx & 15) * 4;
            const size_t gidx = (size_t)(kt * 64 + key) * HDIM + c4;
            float4 kv = *(const float4*)(Kb + gidx);
            uint32_t* kd = &Ks[key][c4];
            kd[0] = f2tf32(kv.x); kd[1] = f2tf32(kv.y);
            kd[2] = f2tf32(kv.z); kd[3] = f2tf32(kv.w);
            float4 vv = *(const float4*)(Vb + gidx);
            VsT[c4 + 0][key] = __float2half(vv.x);
            VsT[c4 + 1][key] = __float2half(vv.y);
            VsT[c4 + 2][key] = __float2half(vv.z);
            VsT[c4 + 3][key] = __float2half(vv.w);
        }
        __syncthreads();

        if (kt * 64 > wbase + 15) continue;   // fully masked for this warp

        // ---- S = Q K^T : 8 n-tiles of 8 keys ----
        float sf[8][4];
        #pragma unroll
        for (int nt = 0; nt < 8; nt++) {
            sf[nt][0] = sf[nt][1] = sf[nt][2] = sf[nt][3] = 0.f;
            const int kr = nt * 8 + g;          // key row for B frag
            #pragma unroll
            for (int kt8 = 0; kt8 < 8; kt8++) {
                uint32_t b0 = Ks[kr][kt8 * 8 + tig];
                uint32_t b1 = Ks[kr][kt8 * 8 + tig + 4];
                mma_tf32(sf[nt], qf[kt8], b0, b1);
            }
        }

        // ---- causal mask (diagonal tiles only) ----
        const int colbase = kt * 64;
        if (colbase + 63 > wbase) {
            #pragma unroll
            for (int nt = 0; nt < 8; nt++) {
                const int c = colbase + nt * 8 + tig * 2;
                if (c     > row0) sf[nt][0] = -CUDART_INF_F;
                if (c + 1 > row0) sf[nt][1] = -CUDART_INF_F;
                if (c     > row1) sf[nt][2] = -CUDART_INF_F;
                if (c + 1 > row1) sf[nt][3] = -CUDART_INF_F;
            }
        }

        // ---- online softmax ----
        float t0 = -CUDART_INF_F, t1 = -CUDART_INF_F;
        #pragma unroll
        for (int nt = 0; nt < 8; nt++) {
            t0 = fmaxf(t0, fmaxf(sf[nt][0], sf[nt][1]));
            t1 = fmaxf(t1, fmaxf(sf[nt][2], sf[nt][3]));
        }
        t0 = fmaxf(t0, __shfl_xor_sync(0xffffffffu, t0, 1));
        t0 = fmaxf(t0, __shfl_xor_sync(0xffffffffu, t0, 2));
        t1 = fmaxf(t1, __shfl_xor_sync(0xffffffffu, t1, 1));
        t1 = fmaxf(t1, __shfl_xor_sync(0xffffffffu, t1, 2));

        const float mn0 = fmaxf(m0, t0);
        const float mn1 = fmaxf(m1, t1);
        const float al0 = __expf(m0 - mn0);   // exp(-inf)=0 on first tile
        const float al1 = __expf(m1 - mn1);
        m0 = mn0; m1 = mn1;
        l0 *= al0; l1 *= al1;
        #pragma unroll
        for (int dt = 0; dt < 8; dt++) {
            of[dt][0] *= al0; of[dt][1] *= al0;
            of[dt][2] *= al1; of[dt][3] *= al1;
        }

        // p = exp(s - m); pack into f16 A-fragments for PV (4 chunks of 16 keys)
        uint32_t pa[4][4];
        #pragma unroll
        for (int nt = 0; nt < 8; nt++) {
            const float p0 = __expf(sf[nt][0] - m0);
            const float p1 = __expf(sf[nt][1] - m0);
            const float p2 = __expf(sf[nt][2] - m1);
            const float p3 = __expf(sf[nt][3] - m1);
            l0 += p0 + p1;
            l1 += p2 + p3;
            const uint32_t lo = h2u(__floats2half2_rn(p0, p1));
            const uint32_t hi = h2u(__floats2half2_rn(p2, p3));
            const int kc  = nt >> 1;
            if ((nt & 1) == 0) { pa[kc][0] = lo; pa[kc][1] = hi; }
            else               { pa[kc][2] = lo; pa[kc][3] = hi; }
        }

        // ---- O += P V : 8 dim-tiles x 4 key-chunks (f16 m16n8k16) ----
        #pragma unroll
        for (int dt = 0; dt < 8; dt++) {
            const int dr = dt * 8 + g;          // dim row of VsT
            #pragma unroll
            for (int kc = 0; kc < 4; kc++) {
                uint32_t b0 = *(const uint32_t*)&VsT[dr][kc * 16 + tig * 2];
                uint32_t b1 = *(const uint32_t*)&VsT[dr][kc * 16 + tig * 2 + 8];
                mma_f16(of[dt], pa[kc], b0, b1);
            }
        }
    }

    // reduce l across the quad (m already uniform)
    l0 += __shfl_xor_sync(0xffffffffu, l0, 1);
    l0 += __shfl_xor_sync(0xffffffffu, l0, 2);
    l1 += __shfl_xor_sync(0xffffffffu, l1, 1);
    l1 += __shfl_xor_sync(0xffffffffu, l1, 2);
    const float inv0 = 1.0f / l0;
    const float inv1 = 1.0f / l1;

    float* Ob = g_O + (size_t)bh * SEQ * HDIM;
    #pragma unroll
    for (int dt = 0; dt < 8; dt++) {
        const int col = dt * 8 + tig * 2;
        *(float2*)&Ob[(size_t)row0 * HDIM + col] =
            make_float2(of[dt][0] * inv0, of[dt][1] * inv0);
        *(float2*)&Ob[(size_t)row1 * HDIM + col] =
            make_float2(of[dt][2] * inv1, of[dt][3] * inv1);
    }
}

// ---------------------------------------------------------------------------
// Kernel 3: output projection via tf32 mma; A gathered from g_O [B,H,T,D].
// ---------------------------------------------------------------------------
__global__ __launch_bounds__(256) void out_gemm(
    const float* __restrict__ W,    // [1024, 1024]
    const float* __restrict__ bias, // [1024]
    float* __restrict__ out)        // [8192, 1024]
{
    __shared__ uint32_t As[2][16][PAD];
    __shared__ uint32_t Bs[2][16][PAD];

    const int tid = threadIdx.x;
    const int wid = tid >> 5;
    const int lane = tid & 31;
    const int g = lane >> 2;
    const int tig = lane & 3;
    const int warp_m = wid >> 1;
    const int warp_n = wid & 1;

    const int bm = blockIdx.y * 128;
    const int bn = blockIdx.x * 128;

    const int ar = tid >> 2;
    const int ac = (tid & 3) * 4;
    const int br = tid >> 5;
    const int bc = (tid & 31) * 4;

    const float* Bp0 = W + (size_t)br * CDIM + bn + bc;
    const float* Bp1 = W + (size_t)(br + 8) * CDIM + bn + bc;

    const int row0 = bm + ar;
    const int row1 = bm + ar + 64;
    const int bb0 = row0 >> 11, t0 = row0 & 2047;
    const int bb1 = row1 >> 11, t1 = row1 & 2047;

    auto aload = [&](int k0, int which) -> float4 {
        const int k = k0 + ac;
        const int h = k >> 6;
        const int d = k & 63;
        const int bb = which ? bb1 : bb0;
        const int t  = which ? t1 : t0;
        return *(const float4*)&g_O[((bb * NHEAD + h) * SEQ + t) * HDIM + d];
    };

    float acc[2][8][4];
    #pragma unroll
    for (int mt = 0; mt < 2; mt++)
        #pragma unroll
        for (int nt = 0; nt < 8; nt++)
            #pragma unroll
            for (int i = 0; i < 4; i++) acc[mt][nt][i] = 0.f;

    auto stage = [&](int buf, float4 a0, float4 a1, float4 b0, float4 b1) {
        As[buf][ac + 0][ar] = f2tf32(a0.x);
        As[buf][ac + 1][ar] = f2tf32(a0.y);
        As[buf][ac + 2][ar] = f2tf32(a0.z);
        As[buf][ac + 3][ar] = f2tf32(a0.w);
        As[buf][ac + 0][ar + 64] = f2tf32(a1.x);
        As[buf][ac + 1][ar + 64] = f2tf32(a1.y);
        As[buf][ac + 2][ar + 64] = f2tf32(a1.z);
        As[buf][ac + 3][ar + 64] = f2tf32(a1.w);
        Bs[buf][br][bc + 0] = f2tf32(b0.x);
        Bs[buf][br][bc + 1] = f2tf32(b0.y);
        Bs[buf][br][bc + 2] = f2tf32(b0.z);
        Bs[buf][br][bc + 3] = f2tf32(b0.w);
        Bs[buf][br + 8][bc + 0] = f2tf32(b1.x);
        Bs[buf][br + 8][bc + 1] = f2tf32(b1.y);
        Bs[buf][br + 8][bc + 2] = f2tf32(b1.z);
        Bs[buf][br + 8][bc + 3] = f2tf32(b1.w);
    };

    stage(0, aload(0, 0), aload(0, 1),
          *(const float4*)(Bp0), *(const float4*)(Bp1));
    __syncthreads();

    const int am = warp_m * 32;
    const int an = warp_n * 64;

    int cur = 0;
    for (int k0 = 0; k0 < CDIM; k0 += 16) {
        float4 a0n, a1n, b0n, b1n;
        const bool has_next = (k0 + 16) < CDIM;
        if (has_next) {
            a0n = aload(k0 + 16, 0);
            a1n = aload(k0 + 16, 1);
            b0n = *(const float4*)(Bp0 + (size_t)(k0 + 16) * CDIM);
            b1n = *(const float4*)(Bp1 + (size_t)(k0 + 16) * CDIM);
        }

        #pragma unroll
        for (int kk = 0; kk < 16; kk += 8) {
            uint32_t Af[2][4], Bf[8][2];
            #pragma unroll
            for (int mt = 0; mt < 2; mt++) {
                const int m0 = am + mt * 16;
                Af[mt][0] = As[cur][kk + tig][m0 + g];
                Af[mt][1] = As[cur][kk + tig][m0 + g + 8];
                Af[mt][2] = As[cur][kk + tig + 4][m0 + g];
                Af[mt][3] = As[cur][kk + tig + 4][m0 + g + 8];
            }
            #pragma unroll
            for (int nt = 0; nt < 8; nt++) {
                const int n0 = an + nt * 8;
                Bf[nt][0] = Bs[cur][kk + tig][n0 + g];
                Bf[nt][1] = Bs[cur][kk + tig + 4][n0 + g];
            }
            #pragma unroll
            for (int mt = 0; mt < 2; mt++)
                #pragma unroll
                for (int nt = 0; nt < 8; nt++)
                    mma_tf32(acc[mt][nt], Af[mt], Bf[nt][0], Bf[nt][1]);
        }

        if (has_next) {
            const int nxt = cur ^ 1;
            stage(nxt, a0n, a1n, b0n, b1n);
            __syncthreads();
            cur = nxt;
        }
    }

    #pragma unroll
    for (int mt = 0; mt < 2; mt++) {
        #pragma unroll
        for (int half = 0; half < 2; half++) {
            const int row = bm + am + mt * 16 + g + half * 8;
            #pragma unroll
            for (int nt = 0; nt < 8; nt++) {
                const int col = bn + an + nt * 8 + tig * 2;
                float v0 = acc[mt][nt][half * 2 + 0] + bias[col];
                float v1 = acc[mt][nt][half * 2 + 1] + bias[col + 1];
                *(float2*)&out[(size_t)row * CDIM + col] = make_float2(v0, v1);
            }
        }
    }
}

// ---------------------------------------------------------------------------
extern "C" void kernel_launch(void* const* d_in, const int* in_sizes, int n_in,
                              void* d_out, int out_size)
{
    const float* x     = (const float*)d_in[0];
    const float* W_qkv = (const float*)d_in[1];
    const float* b_qkv = (const float*)d_in[2];
    const float* W_out = (const float*)d_in[3];
    const float* b_out = (const float*)d_in[4];
    float* out = (float*)d_out;

    qkv_gemm<<<dim3(N3C / 128, (BATCH * SEQ) / 128), 256>>>(x, W_qkv, b_qkv);
    attn_kernel<<<dim3(SEQ / 128, BATCH * NHEAD), 256>>>();
    out_gemm<<<dim3(CDIM / 128, (BATCH * SEQ) / 128), 256>>>(W_out, b_out, out);
}